// round 3
// baseline (speedup 1.0000x reference)
#include <cuda_runtime.h>
#include <cuda_bf16.h>
#include <cstdint>

#define N_NODES 50000
#define N_EDGES 600000
#define D 128
#define BN_EPS 1e-5f

// ---------------- scratch (device globals; no allocation allowed) ----------------
__device__ __align__(256) float g_z[(size_t)N_NODES * D];    // x + agg
__device__ __align__(256) float g_h1[(size_t)N_NODES * D];   // relu(z@W1+b1)
__device__ __align__(256) float g_h2[(size_t)N_NODES * D];   // h1@W2+b2
__device__ __align__(16) float g_sum[D];
__device__ __align__(16) float g_sumsq[D];
__device__ __align__(16) float g_scale[D];
__device__ __align__(16) float g_shift[D];

// ---------------- 1) z = x ; zero BN accumulators ----------------
__global__ void __launch_bounds__(256) init_z(const float* __restrict__ x) {
    size_t i = (size_t)blockIdx.x * 256 + threadIdx.x;   // float4 index
    const size_t n4 = (size_t)N_NODES * (D / 4);
    if (i < n4) {
        reinterpret_cast<float4*>(g_z)[i] = reinterpret_cast<const float4*>(x)[i];
    }
    if (blockIdx.x == 0 && threadIdx.x < D) {
        g_sum[threadIdx.x] = 0.f;
        g_sumsq[threadIdx.x] = 0.f;
    }
}

// ---------------- 2) scatter: z[dst] += x[src]  (one warp per edge) ----------------
// edge_index arrives as int32 (harness downcasts int64 inputs), layout [2, N_EDGES].
__global__ void __launch_bounds__(256) scatter_edges(const int* __restrict__ ei,
                                                     const float* __restrict__ x) {
    int warp = threadIdx.x >> 5;
    int lane = threadIdx.x & 31;
    int e = blockIdx.x * 8 + warp;
    if (e >= N_EDGES) return;
    int s = ei[e];
    int d = ei[N_EDGES + e];
    float4 v = __ldg(reinterpret_cast<const float4*>(x + (size_t)s * D) + lane);
    float* p = g_z + (size_t)d * D + lane * 4;
    asm volatile("red.global.add.v4.f32 [%0], {%1, %2, %3, %4};"
                 :: "l"(p), "f"(v.x), "f"(v.y), "f"(v.z), "f"(v.w) : "memory");
}

// ---------------- 3/4) C = act(A @ W + bias), A:[M,128], W:[128,128] ----------------
// Block tile 128x128, BK=16, 256 threads, 8x8 per thread.
__global__ void __launch_bounds__(256) gemm_bias_act(const float* __restrict__ A,
                                                     const float* __restrict__ W,
                                                     const float* __restrict__ bias,
                                                     float* __restrict__ C,
                                                     int M, int relu) {
    __shared__ __align__(16) float As[16][128];   // transposed A tile: As[k][row]
    __shared__ __align__(16) float Bs[16][128];   // Bs[k][col]
    const int tid = threadIdx.x;
    const int tx = tid & 15;        // col group
    const int ty = tid >> 4;        // row group
    const int rowBase = blockIdx.x * 128;

    float acc[8][8];
    #pragma unroll
    for (int i = 0; i < 8; i++)
        #pragma unroll
        for (int j = 0; j < 8; j++) acc[i][j] = 0.f;

    for (int k0 = 0; k0 < D; k0 += 16) {
        // load A tile (128 rows x 16 k-cols) as float4, store transposed
        #pragma unroll
        for (int it = 0; it < 2; it++) {
            int f = tid + it * 256;          // 0..511 float4 slots
            int r = f >> 2;                  // row in tile
            int c4 = (f & 3) << 2;           // k-col 0,4,8,12
            float4 v = make_float4(0.f, 0.f, 0.f, 0.f);
            int gr = rowBase + r;
            if (gr < M)
                v = *reinterpret_cast<const float4*>(A + (size_t)gr * D + k0 + c4);
            As[c4 + 0][r] = v.x;
            As[c4 + 1][r] = v.y;
            As[c4 + 2][r] = v.z;
            As[c4 + 3][r] = v.w;
        }
        // load W tile (16 k-rows x 128 cols)
        #pragma unroll
        for (int it = 0; it < 2; it++) {
            int f = tid + it * 256;          // 0..511
            int r = f >> 5;                  // k-row 0..15
            int c4 = (f & 31) << 2;          // col
            *reinterpret_cast<float4*>(&Bs[r][c4]) =
                *reinterpret_cast<const float4*>(W + (size_t)(k0 + r) * D + c4);
        }
        __syncthreads();

        #pragma unroll
        for (int k = 0; k < 16; k++) {
            float a[8], b[8];
            *reinterpret_cast<float4*>(&a[0]) = *reinterpret_cast<const float4*>(&As[k][ty * 8]);
            *reinterpret_cast<float4*>(&a[4]) = *reinterpret_cast<const float4*>(&As[k][ty * 8 + 4]);
            *reinterpret_cast<float4*>(&b[0]) = *reinterpret_cast<const float4*>(&Bs[k][tx * 8]);
            *reinterpret_cast<float4*>(&b[4]) = *reinterpret_cast<const float4*>(&Bs[k][tx * 8 + 4]);
            #pragma unroll
            for (int i = 0; i < 8; i++)
                #pragma unroll
                for (int j = 0; j < 8; j++)
                    acc[i][j] = fmaf(a[i], b[j], acc[i][j]);
        }
        __syncthreads();
    }

    // epilogue
    #pragma unroll
    for (int i = 0; i < 8; i++) {
        int gr = rowBase + ty * 8 + i;
        if (gr >= M) continue;
        #pragma unroll
        for (int j = 0; j < 8; j += 4) {
            int gc = tx * 8 + j;
            float4 v;
            v.x = acc[i][j + 0] + bias[gc + 0];
            v.y = acc[i][j + 1] + bias[gc + 1];
            v.z = acc[i][j + 2] + bias[gc + 2];
            v.w = acc[i][j + 3] + bias[gc + 3];
            if (relu) {
                v.x = fmaxf(v.x, 0.f); v.y = fmaxf(v.y, 0.f);
                v.z = fmaxf(v.z, 0.f); v.w = fmaxf(v.w, 0.f);
            }
            *reinterpret_cast<float4*>(C + (size_t)gr * D + gc) = v;
        }
    }
}

// ---------------- 5) per-feature sum / sumsq ----------------
__global__ void __launch_bounds__(128) bn_stats(const float* __restrict__ H) {
    int c = threadIdx.x;   // feature
    float s = 0.f, sq = 0.f;
    for (int r = blockIdx.x; r < N_NODES; r += gridDim.x) {
        float v = H[(size_t)r * D + c];
        s += v;
        sq = fmaf(v, v, sq);
    }
    atomicAdd(&g_sum[c], s);
    atomicAdd(&g_sumsq[c], sq);
}

// ---------------- 6a) fold BN into scale/shift ----------------
__global__ void bn_coef(const float* __restrict__ gamma, const float* __restrict__ beta) {
    int c = threadIdx.x;
    if (c < D) {
        float mean = g_sum[c] * (1.0f / N_NODES);
        float var = g_sumsq[c] * (1.0f / N_NODES) - mean * mean;
        float sc = gamma[c] * rsqrtf(var + BN_EPS);
        g_scale[c] = sc;
        g_shift[c] = beta[c] - mean * sc;
    }
}

// ---------------- 6b) out = h2*scale + shift + x ----------------
__global__ void __launch_bounds__(256) bn_final(const float* __restrict__ H,
                                                const float* __restrict__ X,
                                                float* __restrict__ out) {
    size_t i = (size_t)blockIdx.x * 256 + threadIdx.x;   // float4 index
    const size_t n4 = (size_t)N_NODES * (D / 4);
    if (i >= n4) return;
    int c4 = (int)(i & 31) << 2;   // feature base within row
    float4 h = reinterpret_cast<const float4*>(H)[i];
    float4 x = reinterpret_cast<const float4*>(X)[i];
    float4 o;
    o.x = fmaf(h.x, g_scale[c4 + 0], g_shift[c4 + 0]) + x.x;
    o.y = fmaf(h.y, g_scale[c4 + 1], g_shift[c4 + 1]) + x.y;
    o.z = fmaf(h.z, g_scale[c4 + 2], g_shift[c4 + 2]) + x.z;
    o.w = fmaf(h.w, g_scale[c4 + 3], g_shift[c4 + 3]) + x.w;
    reinterpret_cast<float4*>(out)[i] = o;
}

// ---------------- launcher ----------------
extern "C" void kernel_launch(void* const* d_in, const int* in_sizes, int n_in,
                              void* d_out, int out_size) {
    const float* x = (const float*)d_in[0];
    const int* ei = (const int*)d_in[1];      // int64 in reference, delivered as int32
    const float* W1 = (const float*)d_in[2];
    const float* b1 = (const float*)d_in[3];
    const float* W2 = (const float*)d_in[4];
    const float* b2 = (const float*)d_in[5];
    const float* gamma = (const float*)d_in[6];
    const float* beta = (const float*)d_in[7];
    float* out = (float*)d_out;

    float* z;   cudaGetSymbolAddress((void**)&z,  g_z);
    float* h1;  cudaGetSymbolAddress((void**)&h1, g_h1);
    float* h2;  cudaGetSymbolAddress((void**)&h2, g_h2);

    const int n4 = N_NODES * (D / 4);              // 1.6M float4
    const int copyBlocks = (n4 + 255) / 256;

    init_z<<<copyBlocks, 256>>>(x);
    scatter_edges<<<(N_EDGES + 7) / 8, 256>>>(ei, x);
    gemm_bias_act<<<(N_NODES + 127) / 128, 256>>>(z, W1, b1, h1, N_NODES, 1);
    gemm_bias_act<<<(N_NODES + 127) / 128, 256>>>(h1, W2, b2, h2, N_NODES, 0);
    bn_stats<<<512, 128>>>(h2);
    bn_coef<<<1, 128>>>(gamma, beta);
    bn_final<<<copyBlocks, 256>>>(h2, x, out);
}

// round 4
// speedup vs baseline: 1.0826x; 1.0826x over previous
#include <cuda_runtime.h>
#include <cuda_bf16.h>
#include <cstdint>

#define N_NODES 50000
#define N_EDGES 600000
#define D 128
#define BN_EPS 1e-5f

// ---------------- scratch ----------------
__device__ __align__(256) float g_z[(size_t)N_NODES * D];    // x + agg
__device__ __align__(256) float g_h1[(size_t)N_NODES * D];   // relu(z@W1+b1)
__device__ __align__(256) float g_h2[(size_t)N_NODES * D];   // h1@W2+b2
__device__ __align__(16) float g_sum[D];
__device__ __align__(16) float g_sumsq[D];
__device__ __align__(16) float g_scale[D];
__device__ __align__(16) float g_shift[D];

// ---------------- 1) z = x ; zero BN accumulators ----------------
__global__ void __launch_bounds__(256) init_z(const float* __restrict__ x) {
    size_t i = (size_t)blockIdx.x * 256 + threadIdx.x;
    const size_t n4 = (size_t)N_NODES * (D / 4);
    if (i < n4) {
        reinterpret_cast<float4*>(g_z)[i] = reinterpret_cast<const float4*>(x)[i];
    }
    if (blockIdx.x == 0 && threadIdx.x < D) {
        g_sum[threadIdx.x] = 0.f;
        g_sumsq[threadIdx.x] = 0.f;
    }
}

// ---------------- 2) scatter: z[dst] += x[src]  (one warp per edge) ----------------
__global__ void __launch_bounds__(256) scatter_edges(const int* __restrict__ ei,
                                                     const float* __restrict__ x) {
    int warp = threadIdx.x >> 5;
    int lane = threadIdx.x & 31;
    int e = blockIdx.x * 8 + warp;
    if (e >= N_EDGES) return;
    int s = ei[e];
    int d = ei[N_EDGES + e];
    float4 v = __ldg(reinterpret_cast<const float4*>(x + (size_t)s * D) + lane);
    float* p = g_z + (size_t)d * D + lane * 4;
    asm volatile("red.global.add.v4.f32 [%0], {%1, %2, %3, %4};"
                 :: "l"(p), "f"(v.x), "f"(v.y), "f"(v.z), "f"(v.w) : "memory");
}

// ---------------- 3/4) tensor-core GEMM: C = act(A @ W + bias) ----------------
// bf16x3 split (hi/lo) via mma.sync m16n8k16 -> fp32-class accuracy on HMMA pipe.
// Block: 128 rows x 128 cols, 256 threads (8 warps: 4 along M x 2 along N).
// K=128 processed in two halves of 64 staged through smem.

#define ASTRIDE 72   // bf16 elements per smem row (64 + 8 pad -> conflict-free b32 LDS)

#define MMA_BF16(d, A0, A1, A2, A3, B0, B1)                                   \
    asm volatile("mma.sync.aligned.m16n8k16.row.col.f32.bf16.bf16.f32 "       \
                 "{%0,%1,%2,%3}, {%4,%5,%6,%7}, {%8,%9}, {%0,%1,%2,%3};"      \
                 : "+f"(d[0]), "+f"(d[1]), "+f"(d[2]), "+f"(d[3])             \
                 : "r"(A0), "r"(A1), "r"(A2), "r"(A3), "r"(B0), "r"(B1))

__global__ void __launch_bounds__(256) gemm_mma(const float* __restrict__ A,
                                                const float* __restrict__ W,
                                                const float* __restrict__ bias,
                                                float* __restrict__ C,
                                                int M, int relu) {
    extern __shared__ __align__(16) unsigned char smem_raw[];
    __nv_bfloat16* Ah = reinterpret_cast<__nv_bfloat16*>(smem_raw);      // [128][ASTRIDE]
    __nv_bfloat16* Al = Ah + 128 * ASTRIDE;
    __nv_bfloat16* Bh = Al + 128 * ASTRIDE;   // W^T hi: [n][k]
    __nv_bfloat16* Bl = Bh + 128 * ASTRIDE;

    const int tid  = threadIdx.x;
    const int lane = tid & 31;
    const int wid  = tid >> 5;
    const int g    = lane >> 2;       // 0..7
    const int tig  = lane & 3;        // 0..3
    const int wm   = wid & 3;         // warp row group (x32 rows)
    const int wn   = wid >> 2;        // warp col group (x64 cols)
    const int rowBase = blockIdx.x * 128;

    float acc[2][8][4];
    #pragma unroll
    for (int i = 0; i < 2; i++)
        #pragma unroll
        for (int j = 0; j < 8; j++)
            #pragma unroll
            for (int c = 0; c < 4; c++) acc[i][j][c] = 0.f;

    for (int k0 = 0; k0 < 128; k0 += 64) {
        if (k0) __syncthreads();

        // --- stage A half-tile [128 rows x 64 k] as hi/lo bf16 ---
        #pragma unroll
        for (int it = 0; it < 8; it++) {
            int f = tid + it * 256;            // 0..2047 float4 slots
            int r = f >> 4;                    // row 0..127
            int c = (f & 15) << 2;             // k-col 0..60
            int gr = rowBase + r;
            float4 v = make_float4(0.f, 0.f, 0.f, 0.f);
            if (gr < M) v = *reinterpret_cast<const float4*>(A + (size_t)gr * D + k0 + c);
            float vv[4] = {v.x, v.y, v.z, v.w};
            #pragma unroll
            for (int dd = 0; dd < 4; dd++) {
                __nv_bfloat16 h = __float2bfloat16(vv[dd]);
                Ah[r * ASTRIDE + c + dd] = h;
                Al[r * ASTRIDE + c + dd] = __float2bfloat16(vv[dd] - __bfloat162float(h));
            }
        }
        // --- stage W^T half-tile [128 n x 64 k] as hi/lo bf16 ---
        #pragma unroll
        for (int it = 0; it < 8; it++) {
            int f = tid + it * 256;            // 0..2047
            int k = f >> 5;                    // 0..63
            int n = (f & 31) << 2;             // 0..124
            float4 v = *reinterpret_cast<const float4*>(W + (size_t)(k0 + k) * D + n);
            float vv[4] = {v.x, v.y, v.z, v.w};
            #pragma unroll
            for (int dd = 0; dd < 4; dd++) {
                __nv_bfloat16 h = __float2bfloat16(vv[dd]);
                Bh[(n + dd) * ASTRIDE + k] = h;
                Bl[(n + dd) * ASTRIDE + k] = __float2bfloat16(vv[dd] - __bfloat162float(h));
            }
        }
        __syncthreads();

        // --- 4 k-steps of 16 ---
        #pragma unroll
        for (int ks = 0; ks < 4; ks++) {
            const int k = ks * 16;
            uint32_t ah[2][4], al[2][4];
            #pragma unroll
            for (int i = 0; i < 2; i++) {
                int r0 = wm * 32 + i * 16 + g;
                ah[i][0] = *reinterpret_cast<const uint32_t*>(&Ah[(r0    ) * ASTRIDE + k + tig * 2]);
                ah[i][1] = *reinterpret_cast<const uint32_t*>(&Ah[(r0 + 8) * ASTRIDE + k + tig * 2]);
                ah[i][2] = *reinterpret_cast<const uint32_t*>(&Ah[(r0    ) * ASTRIDE + k + 8 + tig * 2]);
                ah[i][3] = *reinterpret_cast<const uint32_t*>(&Ah[(r0 + 8) * ASTRIDE + k + 8 + tig * 2]);
                al[i][0] = *reinterpret_cast<const uint32_t*>(&Al[(r0    ) * ASTRIDE + k + tig * 2]);
                al[i][1] = *reinterpret_cast<const uint32_t*>(&Al[(r0 + 8) * ASTRIDE + k + tig * 2]);
                al[i][2] = *reinterpret_cast<const uint32_t*>(&Al[(r0    ) * ASTRIDE + k + 8 + tig * 2]);
                al[i][3] = *reinterpret_cast<const uint32_t*>(&Al[(r0 + 8) * ASTRIDE + k + 8 + tig * 2]);
            }
            #pragma unroll
            for (int j = 0; j < 8; j++) {
                int n = wn * 64 + j * 8 + g;
                uint32_t bh0 = *reinterpret_cast<const uint32_t*>(&Bh[n * ASTRIDE + k + tig * 2]);
                uint32_t bh1 = *reinterpret_cast<const uint32_t*>(&Bh[n * ASTRIDE + k + 8 + tig * 2]);
                uint32_t bl0 = *reinterpret_cast<const uint32_t*>(&Bl[n * ASTRIDE + k + tig * 2]);
                uint32_t bl1 = *reinterpret_cast<const uint32_t*>(&Bl[n * ASTRIDE + k + 8 + tig * 2]);
                #pragma unroll
                for (int i = 0; i < 2; i++) {
                    MMA_BF16(acc[i][j], ah[i][0], ah[i][1], ah[i][2], ah[i][3], bh0, bh1);
                    MMA_BF16(acc[i][j], ah[i][0], ah[i][1], ah[i][2], ah[i][3], bl0, bl1);
                    MMA_BF16(acc[i][j], al[i][0], al[i][1], al[i][2], al[i][3], bh0, bh1);
                }
            }
        }
    }

    // --- epilogue: bias (+ReLU), fp32 stores ---
    #pragma unroll
    for (int i = 0; i < 2; i++) {
        int row0 = rowBase + wm * 32 + i * 16 + g;
        #pragma unroll
        for (int j = 0; j < 8; j++) {
            int col = wn * 64 + j * 8 + tig * 2;
            float bb0 = bias[col], bb1 = bias[col + 1];
            float v00 = acc[i][j][0] + bb0, v01 = acc[i][j][1] + bb1;   // row0
            float v10 = acc[i][j][2] + bb0, v11 = acc[i][j][3] + bb1;   // row0+8
            if (relu) {
                v00 = fmaxf(v00, 0.f); v01 = fmaxf(v01, 0.f);
                v10 = fmaxf(v10, 0.f); v11 = fmaxf(v11, 0.f);
            }
            if (row0 < M)
                *reinterpret_cast<float2*>(C + (size_t)row0 * D + col) = make_float2(v00, v01);
            if (row0 + 8 < M)
                *reinterpret_cast<float2*>(C + (size_t)(row0 + 8) * D + col) = make_float2(v10, v11);
        }
    }
}

#define GEMM_SMEM (4 * 128 * ASTRIDE * 2)   // 73728 bytes

// ---------------- 5) per-feature sum / sumsq ----------------
__global__ void __launch_bounds__(128) bn_stats(const float* __restrict__ H) {
    int c = threadIdx.x;
    float s = 0.f, sq = 0.f;
    for (int r = blockIdx.x; r < N_NODES; r += gridDim.x) {
        float v = H[(size_t)r * D + c];
        s += v;
        sq = fmaf(v, v, sq);
    }
    atomicAdd(&g_sum[c], s);
    atomicAdd(&g_sumsq[c], sq);
}

// ---------------- 6a) fold BN into scale/shift ----------------
__global__ void bn_coef(const float* __restrict__ gamma, const float* __restrict__ beta) {
    int c = threadIdx.x;
    if (c < D) {
        float mean = g_sum[c] * (1.0f / N_NODES);
        float var = g_sumsq[c] * (1.0f / N_NODES) - mean * mean;
        float sc = gamma[c] * rsqrtf(var + BN_EPS);
        g_scale[c] = sc;
        g_shift[c] = beta[c] - mean * sc;
    }
}

// ---------------- 6b) out = h2*scale + shift + x ----------------
__global__ void __launch_bounds__(256) bn_final(const float* __restrict__ H,
                                                const float* __restrict__ X,
                                                float* __restrict__ out) {
    size_t i = (size_t)blockIdx.x * 256 + threadIdx.x;
    const size_t n4 = (size_t)N_NODES * (D / 4);
    if (i >= n4) return;
    int c4 = (int)(i & 31) << 2;
    float4 h = reinterpret_cast<const float4*>(H)[i];
    float4 x = reinterpret_cast<const float4*>(X)[i];
    float4 o;
    o.x = fmaf(h.x, g_scale[c4 + 0], g_shift[c4 + 0]) + x.x;
    o.y = fmaf(h.y, g_scale[c4 + 1], g_shift[c4 + 1]) + x.y;
    o.z = fmaf(h.z, g_scale[c4 + 2], g_shift[c4 + 2]) + x.z;
    o.w = fmaf(h.w, g_scale[c4 + 3], g_shift[c4 + 3]) + x.w;
    reinterpret_cast<float4*>(out)[i] = o;
}

// ---------------- launcher ----------------
extern "C" void kernel_launch(void* const* d_in, const int* in_sizes, int n_in,
                              void* d_out, int out_size) {
    const float* x = (const float*)d_in[0];
    const int* ei = (const int*)d_in[1];      // int64 in reference, delivered as int32
    const float* W1 = (const float*)d_in[2];
    const float* b1 = (const float*)d_in[3];
    const float* W2 = (const float*)d_in[4];
    const float* b2 = (const float*)d_in[5];
    const float* gamma = (const float*)d_in[6];
    const float* beta = (const float*)d_in[7];
    float* out = (float*)d_out;

    float* z;   cudaGetSymbolAddress((void**)&z,  g_z);
    float* h1;  cudaGetSymbolAddress((void**)&h1, g_h1);
    float* h2;  cudaGetSymbolAddress((void**)&h2, g_h2);

    cudaFuncSetAttribute(gemm_mma, cudaFuncAttributeMaxDynamicSharedMemorySize, GEMM_SMEM);

    const int n4 = N_NODES * (D / 4);
    const int copyBlocks = (n4 + 255) / 256;
    const int gemmBlocks = (N_NODES + 127) / 128;

    init_z<<<copyBlocks, 256>>>(x);
    scatter_edges<<<(N_EDGES + 7) / 8, 256>>>(ei, x);
    gemm_mma<<<gemmBlocks, 256, GEMM_SMEM>>>(z, W1, b1, h1, N_NODES, 1);
    gemm_mma<<<gemmBlocks, 256, GEMM_SMEM>>>(h1, W2, b2, h2, N_NODES, 0);
    bn_stats<<<512, 128>>>(h2);
    bn_coef<<<1, 128>>>(gamma, beta);
    bn_final<<<copyBlocks, 256>>>(h2, x, out);
}